// round 14
// baseline (speedup 1.0000x reference)
#include <cuda_runtime.h>
#include <cuda_fp16.h>
#include <cstdint>

// ---------------------------------------------------------------- constants
#define HH 80
#define WW 80
#define CH 256
#define NC 22
#define DIM 256
#define P 25600              // 4*80*80 pixels
#define NCHUNK 36            // 9 taps * 4 chunks of 64 channels
// stage layout: B only, 8K (64 d-rows x 64 ch fp16)
#define STAGE 8192
#define NSTAGE 2

// device scratch
__device__ uint32_t g_selh2[P * 9];    // sel*norm as broadcast half2
__device__ uint4 g_w[144 * 512];       // weight fp16 smem-images (pre-swizzled 8KB blocks)
// x fp16 fragment-major, COALESCED: [(ct*2+kp)][p][c4] 16B units
__device__ uint4 g_xa[8 * P * 4];

// ---------------------------------------------------------------- helpers
static __device__ __forceinline__ uint32_t smem_u32(const void* p) {
    uint32_t a;
    asm("{ .reg .u64 t; cvta.to.shared.u64 t, %1; cvt.u32.u64 %0, t; }" : "=r"(a) : "l"(p));
    return a;
}

#define LDSM4(r, addr) \
    asm volatile("ldmatrix.sync.aligned.m8n8.x4.shared.b16 {%0,%1,%2,%3},[%4];" \
        : "=r"((r)[0]), "=r"((r)[1]), "=r"((r)[2]), "=r"((r)[3]) : "r"(addr))
#define MMA4(acc, a0, a1, a2, a3, b0, b1) \
    asm volatile("mma.sync.aligned.m16n8k16.row.col.f32.f16.f16.f32 " \
        "{%0,%1,%2,%3},{%4,%5,%6,%7},{%8,%9},{%0,%1,%2,%3};" \
        : "+f"((acc)[0]), "+f"((acc)[1]), "+f"((acc)[2]), "+f"((acc)[3]) \
        : "r"(a0), "r"(a1), "r"(a2), "r"(a3), "r"(b0), "r"(b1))
#define CPA(dst, src) \
    asm volatile("cp.async.cg.shared.global [%0], [%1], 16;" :: "r"(dst), "l"(src))

static __device__ __forceinline__ uint32_t hmul2u(uint32_t a, uint32_t s) {
    uint32_t r;
    asm("mul.rn.f16x2 %0, %1, %2;" : "=r"(r) : "r"(a), "r"(s));
    return r;
}
static __device__ __forceinline__ int clampP(int v) {
    return v < 0 ? 0 : (v >= P ? P - 1 : v);
}

// ---------------------------------------------------------------- fused prep kernel
// blocks [0,400): selnorm (4 lanes/pixel) -> g_selh2
// blocks [400,3600): x -> fp16 fragment-major g_xa (coalesced region layout)
// blocks [3600,3888): weight -> fp16 smem-image (coalesced: d fastest)
__global__ void prep_all(const float* __restrict__ x,
                         const float* __restrict__ seg,
                         const float* __restrict__ wgt)
{
    int b = blockIdx.x;
    if (b < 400) {
        // ---- selnorm ----
        int gid = b * 256 + threadIdx.x;       // P*4 threads
        int p = gid >> 2, q = gid & 3;
        int w = p % WW, h = (p / WW) % HH;
        int c0 = q * 6;
        int ncl = (q == 3) ? 4 : 6;

        const float* cp_ = seg + (size_t)p * NC + c0;
        float cv[6];
#pragma unroll
        for (int i = 0; i < 6; i++) cv[i] = (i < ncl) ? cp_[i] : -1e30f;

        float m = cv[0];
#pragma unroll
        for (int i = 1; i < 6; i++) m = fmaxf(m, cv[i]);
        m = fmaxf(m, __shfl_xor_sync(0xffffffffu, m, 1));
        m = fmaxf(m, __shfl_xor_sync(0xffffffffu, m, 2));

        float sel[9];
        int cnt = 0;
#pragma unroll
        for (int k = 0; k < 9; k++) {
            int dh = k / 3 - 1, dw = k % 3 - 1;
            int hh = h + dh, ww = w + dw;
            float s = 0.0f;
            if (hh >= 0 && hh < HH && ww >= 0 && ww < WW) {
                const float* nb = seg + (size_t)(p + dh * WW + dw) * NC + c0;
#pragma unroll
                for (int i = 0; i < 6; i++)
                    if (i < ncl && cv[i] == m) s += nb[i];
            }
            s += __shfl_xor_sync(0xffffffffu, s, 1);
            s += __shfl_xor_sync(0xffffffffu, s, 2);
            sel[k] = s;
            if (s != 0.0f) cnt++;
        }
        float nrm = (cnt > 0) ? 9.0f / (float)cnt : 0.0f;
        for (int k = q; k < 9; k += 4) {
            __half hv = __float2half_rn(sel[k] * nrm);
            uint32_t u = (uint32_t)__half_as_ushort(hv);
            g_selh2[p * 9 + k] = u | (u << 16);
        }
    } else if (b < 3600) {
        // ---- x -> fp16 fragment-major (coalesced regions) ----
        int gid = (b - 400) * 256 + threadIdx.x;   // P*32 threads
        int c4 = gid & 3;
        int kp = (gid >> 2) & 1;
        int ct = (gid >> 3) & 3;
        int p  = gid >> 5;

        const float* src = x + (size_t)p * CH + ct * 64 + kp * 32 + c4 * 2;
        uint32_t h4[4];
#pragma unroll
        for (int j = 0; j < 4; j++) {
            int off = j * 8;                      // j: +0, +8, +16, +24
            __half h0 = __float2half_rn(src[off]);
            __half h1 = __float2half_rn(src[off + 1]);
            h4[j] = (uint32_t)__half_as_ushort(h0) | ((uint32_t)__half_as_ushort(h1) << 16);
        }
        size_t idx = ((size_t)(ct * 2 + kp) * P + p) * 4 + c4;
        g_xa[idx] = make_uint4(h4[0], h4[1], h4[2], h4[3]);
    } else {
        // ---- weight -> fp16 pre-swizzled image (d varies fastest: coalesced) ----
        int id = (b - 3600) * 256 + threadIdx.x;   // 73728 threads
        int row  = id & 63;            // d_local (fastest)
        int cc8  = (id >> 6) & 7;
        int blk  = id >> 9;            // 0..143
        int nb4  = blk & 3;
        int chunk = blk >> 2;
        int ktap = chunk >> 2, ct = chunk & 3;
        int d  = nb4 * 64 + row;
        int c0 = ct * 64 + cc8 * 8;

        uint32_t h4[4];
#pragma unroll
        for (int j = 0; j < 4; j++) {
            float v0 = wgt[(size_t)(c0 + 2*j)     * (9 * DIM) + ktap * DIM + d];
            float v1 = wgt[(size_t)(c0 + 2*j + 1) * (9 * DIM) + ktap * DIM + d];
            __half h0 = __float2half_rn(v0);
            __half h1 = __float2half_rn(v1);
            h4[j] = (uint32_t)__half_as_ushort(h0) | ((uint32_t)__half_as_ushort(h1) << 16);
        }
        int idx = blk * 512 + row * 8 + (cc8 ^ (row & 7));
        g_w[idx] = make_uint4(h4[0], h4[1], h4[2], h4[3]);
    }
}

// ---------------------------------------------------------------- HMMA implicit GEMM
// CTA 128(M) x 64(N), 256 threads, 8 warps (4M x 2N), warp tile 32x32.
// A fragments loaded DIRECTLY from gmem (coalesced 512B warp segments),
// sel folded in registers; only B (8KB) through SMEM. 3 CTAs/SM.
__global__ __launch_bounds__(256, 3) void pconv_mma(float* __restrict__ out)
{
    extern __shared__ __align__(1024) char smem[];
    const uint32_t sb = smem_u32(smem);
    const int tid = threadIdx.x, wid = tid >> 5, lid = tid & 31;
    const int p0 = blockIdx.x * 128;
    const int nblk = blockIdx.y;            // 0..3 (64-wide N block)
    const int wm = wid & 3, wn = wid >> 2;  // 4 M-quarters x 2 N-halves(32)

    const int rlane = lid >> 2;             // fragment row within m8 (0..7)
    const int c4 = lid & 3;

    // B ldmatrix lane addressing
    const int bi = lid >> 3;                   // 0..3
    const int bnt = bi >> 1, bkh = bi & 1;
    const int brow = wn * 32 + bnt * 8 + (lid & 7);
    const int bsw  = lid & 7;

    float acc[2][4][4];
#pragma unroll
    for (int i = 0; i < 2; i++)
#pragma unroll
        for (int j = 0; j < 4; j++)
#pragma unroll
            for (int r = 0; r < 4; r++) acc[i][j][r] = 0.0f;

    auto cpB = [&](int chunk, int s) {
        uint32_t st = sb + s * STAGE;
        const uint4* wp = g_w + (size_t)(chunk * 4 + nblk) * 512;
        CPA(st + tid * 16,         wp + tid);
        CPA(st + (tid + 256) * 16, wp + tid + 256);
        asm volatile("cp.async.commit_group;" ::: "memory");
    };

    // prologue
    cpB(0, 0);

#pragma unroll 1
    for (int c = 0; c < NCHUNK; c++) {
        const int s = c & 1;
        const int ktap = c >> 2, ct = c & 3;
        const int delta = (ktap / 3 - 1) * WW + (ktap % 3 - 1);

        // ---- A fragment LDGs (coalesced 512B segments) + sel, before barrier ----
        uint4 L[2][2][2];          // [mt][kp][rowhalf]
        uint32_t sv[2][2];         // [mt][rowhalf]
#pragma unroll
        for (int mt = 0; mt < 2; mt++) {
            int r0 = p0 + wm * 32 + mt * 16 + rlane;
            sv[mt][0] = g_selh2[r0 * 9 + ktap];
            sv[mt][1] = g_selh2[(r0 + 8) * 9 + ktap];
            int n0 = clampP(r0 + delta);
            int n1 = clampP(r0 + 8 + delta);
#pragma unroll
            for (int kp = 0; kp < 2; kp++) {
                size_t reg = (size_t)(ct * 2 + kp) * P;
                L[mt][kp][0] = g_xa[(reg + n0) * 4 + c4];
                L[mt][kp][1] = g_xa[(reg + n1) * 4 + c4];
            }
        }

        asm volatile("cp.async.wait_group 0;" ::: "memory");   // cpB(c) landed
        __syncthreads();                                       // stage s^1 readers done
        if (c + 1 < NCHUNK) cpB(c + 1, s ^ 1);

        // ---- fold sel into A fragments (regs) ----
#pragma unroll
        for (int mt = 0; mt < 2; mt++)
#pragma unroll
            for (int kp = 0; kp < 2; kp++)
#pragma unroll
                for (int rh = 0; rh < 2; rh++) {
                    L[mt][kp][rh].x = hmul2u(L[mt][kp][rh].x, sv[mt][rh]);
                    L[mt][kp][rh].y = hmul2u(L[mt][kp][rh].y, sv[mt][rh]);
                    L[mt][kp][rh].z = hmul2u(L[mt][kp][rh].z, sv[mt][rh]);
                    L[mt][kp][rh].w = hmul2u(L[mt][kp][rh].w, sv[mt][rh]);
                }

        // ---- compute: B from smem, A from L regs ----
        const uint32_t Bp = sb + s * STAGE;
#pragma unroll
        for (int ks = 0; ks < 4; ks++) {
            const int kp = ks >> 1, kl = ks & 1;
            uint32_t bfr[4][2];
#pragma unroll
            for (int ntp = 0; ntp < 2; ntp++) {
                uint32_t off = (uint32_t)(brow + ntp * 16) * 128
                             + (((ks * 2 + bkh) ^ bsw) << 4);
                uint32_t r[4];
                LDSM4(r, Bp + off);
                bfr[ntp*2+0][0] = r[0]; bfr[ntp*2+0][1] = r[1];
                bfr[ntp*2+1][0] = r[2]; bfr[ntp*2+1][1] = r[3];
            }
#pragma unroll
            for (int mt = 0; mt < 2; mt++) {
                // a0=(r,klo), a1=(r+8,klo), a2=(r,khi), a3=(r+8,khi)
                uint32_t a0 = kl ? L[mt][kp][0].z : L[mt][kp][0].x;
                uint32_t a1 = kl ? L[mt][kp][1].z : L[mt][kp][1].x;
                uint32_t a2 = kl ? L[mt][kp][0].w : L[mt][kp][0].y;
                uint32_t a3 = kl ? L[mt][kp][1].w : L[mt][kp][1].y;
#pragma unroll
                for (int nt = 0; nt < 4; nt++)
                    MMA4(acc[mt][nt], a0, a1, a2, a3, bfr[nt][0], bfr[nt][1]);
            }
        }
    }

    // epilogue
#pragma unroll
    for (int mt = 0; mt < 2; mt++) {
        int r0 = p0 + wm * 32 + mt * 16 + rlane;
#pragma unroll
        for (int nt = 0; nt < 4; nt++) {
            int col = nblk * 64 + wn * 32 + nt * 8 + c4 * 2;
            float2* d0 = (float2*)(out + (size_t)r0 * DIM + col);
            float2* d1 = (float2*)(out + (size_t)(r0 + 8) * DIM + col);
            *d0 = make_float2(acc[mt][nt][0], acc[mt][nt][1]);
            *d1 = make_float2(acc[mt][nt][2], acc[mt][nt][3]);
        }
    }
}

// ---------------------------------------------------------------- launch
extern "C" void kernel_launch(void* const* d_in, const int* in_sizes, int n_in,
                              void* d_out, int out_size)
{
    const float* x   = (const float*)d_in[0];
    const float* seg = (const float*)d_in[1];
    const float* wgt = (const float*)d_in[2];
    float* out = (float*)d_out;

    cudaFuncSetAttribute(pconv_mma, cudaFuncAttributeMaxDynamicSharedMemorySize,
                         NSTAGE * STAGE);

    prep_all<<<3888, 256>>>(x, seg, wgt);

    dim3 grid(P / 128, 4);
    pconv_mma<<<grid, 256, NSTAGE * STAGE>>>(out);
}

// round 15
// speedup vs baseline: 1.3553x; 1.3553x over previous
#include <cuda_runtime.h>
#include <cuda_fp16.h>
#include <cstdint>

// ---------------------------------------------------------------- constants
#define HH 80
#define WW 80
#define CH 256
#define NC 22
#define DIM 256
#define P 25600              // 4*80*80 pixels
#define NCHUNK 36            // 9 taps * 4 chunks of 64 channels
#define KSPLIT 2
#define CPK (NCHUNK / KSPLIT)    // 18 chunks per K-slice
// stage layout: A 16K | B 16K
#define STAGE 32768
#define NSTAGE 2

// device scratch
__device__ uint32_t g_selh2[P * 9];    // sel*norm as broadcast half2
__device__ uint4 g_w[144 * 512];       // weight fp16 smem-images (pre-swizzled 8KB blocks)
__device__ uint4 g_xf[4 * P * 8];      // x fp16, [ct][p][g] 16B groups
__device__ float g_part[KSPLIT][P * DIM];   // split-K partials (52 MB)

// ---------------------------------------------------------------- helpers
static __device__ __forceinline__ uint32_t smem_u32(const void* p) {
    uint32_t a;
    asm("{ .reg .u64 t; cvta.to.shared.u64 t, %1; cvt.u32.u64 %0, t; }" : "=r"(a) : "l"(p));
    return a;
}

#define LDSM4(r, addr) \
    asm volatile("ldmatrix.sync.aligned.m8n8.x4.shared.b16 {%0,%1,%2,%3},[%4];" \
        : "=r"((r)[0]), "=r"((r)[1]), "=r"((r)[2]), "=r"((r)[3]) : "r"(addr))
#define MMA(acc, a, b) \
    asm volatile("mma.sync.aligned.m16n8k16.row.col.f32.f16.f16.f32 " \
        "{%0,%1,%2,%3},{%4,%5,%6,%7},{%8,%9},{%0,%1,%2,%3};" \
        : "+f"((acc)[0]), "+f"((acc)[1]), "+f"((acc)[2]), "+f"((acc)[3]) \
        : "r"((a)[0]), "r"((a)[1]), "r"((a)[2]), "r"((a)[3]), "r"((b)[0]), "r"((b)[1]))
#define CPA(dst, src) \
    asm volatile("cp.async.cg.shared.global [%0], [%1], 16;" :: "r"(dst), "l"(src))

static __device__ __forceinline__ uint32_t hmul2u(uint32_t a, uint32_t s) {
    uint32_t r;
    asm("mul.rn.f16x2 %0, %1, %2;" : "=r"(r) : "r"(a), "r"(s));
    return r;
}

// ---------------------------------------------------------------- fused prep kernel
// blocks [0,400): selnorm (4 lanes/pixel) -> g_selh2
// blocks [400,3600): x -> fp16
// blocks [3600,3888): weight -> fp16 smem-image (coalesced: d fastest)
__global__ void prep_all(const float* __restrict__ x,
                         const float* __restrict__ seg,
                         const float* __restrict__ wgt)
{
    int b = blockIdx.x;
    if (b < 400) {
        // ---- selnorm ----
        int gid = b * 256 + threadIdx.x;       // P*4 threads
        int p = gid >> 2, q = gid & 3;
        int w = p % WW, h = (p / WW) % HH;
        int c0 = q * 6;
        int ncl = (q == 3) ? 4 : 6;

        const float* cp_ = seg + (size_t)p * NC + c0;
        float cv[6];
#pragma unroll
        for (int i = 0; i < 6; i++) cv[i] = (i < ncl) ? cp_[i] : -1e30f;

        float m = cv[0];
#pragma unroll
        for (int i = 1; i < 6; i++) m = fmaxf(m, cv[i]);
        m = fmaxf(m, __shfl_xor_sync(0xffffffffu, m, 1));
        m = fmaxf(m, __shfl_xor_sync(0xffffffffu, m, 2));

        float sel[9];
        int cnt = 0;
#pragma unroll
        for (int k = 0; k < 9; k++) {
            int dh = k / 3 - 1, dw = k % 3 - 1;
            int hh = h + dh, ww = w + dw;
            float s = 0.0f;
            if (hh >= 0 && hh < HH && ww >= 0 && ww < WW) {
                const float* nb = seg + (size_t)(p + dh * WW + dw) * NC + c0;
#pragma unroll
                for (int i = 0; i < 6; i++)
                    if (i < ncl && cv[i] == m) s += nb[i];
            }
            s += __shfl_xor_sync(0xffffffffu, s, 1);
            s += __shfl_xor_sync(0xffffffffu, s, 2);
            sel[k] = s;
            if (s != 0.0f) cnt++;
        }
        float nrm = (cnt > 0) ? 9.0f / (float)cnt : 0.0f;
        for (int k = q; k < 9; k += 4) {
            __half hv = __float2half_rn(sel[k] * nrm);
            uint32_t u = (uint32_t)__half_as_ushort(hv);
            g_selh2[p * 9 + k] = u | (u << 16);
        }
    } else if (b < 3600) {
        // ---- x -> fp16 ----
        int gid = (b - 400) * 256 + threadIdx.x;   // P*32 threads
        int g8 = gid & 31;
        int p  = gid >> 5;
        int c0 = g8 * 8;
        int ct = c0 >> 6, g = (c0 >> 3) & 7;

        const float* src = x + (size_t)p * CH + c0;
        uint32_t h4[4];
#pragma unroll
        for (int j = 0; j < 4; j++) {
            __half h0 = __float2half_rn(src[2*j]);
            __half h1 = __float2half_rn(src[2*j+1]);
            h4[j] = (uint32_t)__half_as_ushort(h0) | ((uint32_t)__half_as_ushort(h1) << 16);
        }
        g_xf[(ct * P + p) * 8 + g] = make_uint4(h4[0], h4[1], h4[2], h4[3]);
    } else {
        // ---- weight -> fp16 pre-swizzled image (d varies fastest: coalesced) ----
        int id = (b - 3600) * 256 + threadIdx.x;   // 73728 threads
        int row  = id & 63;            // d_local (fastest)
        int cc8  = (id >> 6) & 7;
        int blk  = id >> 9;            // 0..143
        int nb4  = blk & 3;
        int chunk = blk >> 2;
        int ktap = chunk >> 2, ct = chunk & 3;
        int d  = nb4 * 64 + row;
        int c0 = ct * 64 + cc8 * 8;

        uint32_t h4[4];
#pragma unroll
        for (int j = 0; j < 4; j++) {
            float v0 = wgt[(size_t)(c0 + 2*j)     * (9 * DIM) + ktap * DIM + d];
            float v1 = wgt[(size_t)(c0 + 2*j + 1) * (9 * DIM) + ktap * DIM + d];
            __half h0 = __float2half_rn(v0);
            __half h1 = __float2half_rn(v1);
            h4[j] = (uint32_t)__half_as_ushort(h0) | ((uint32_t)__half_as_ushort(h1) << 16);
        }
        int idx = blk * 512 + row * 8 + (cc8 ^ (row & 7));
        g_w[idx] = make_uint4(h4[0], h4[1], h4[2], h4[3]);
    }
}

// ---------------------------------------------------------------- HMMA implicit GEMM (split-K)
// CTA 128(M) x 128(N) x K-slice, 256 threads, 8 warps (4M x 2N), warp 32x64.
// Identical per-chunk pipeline to the proven R8 kernel; each CTA covers 18
// chunks and writes an fp32 partial. 800 CTAs / 296 slots -> 0.90 wave util.
__global__ __launch_bounds__(256, 2) void pconv_mma()
{
    extern __shared__ __align__(1024) char smem[];
    const uint32_t sb = smem_u32(smem);
    const int tid = threadIdx.x, wid = tid >> 5, lid = tid & 31;
    const int p0 = blockIdx.x * 128;
    const int nblk = blockIdx.y;            // 0..1 (128-wide N block)
    const int kz = blockIdx.z;              // K-slice
    const int c0 = kz * CPK;
    const int wm = wid & 3, wn = wid >> 2;  // 4 M-quarters x 2 N-halves(64)

    // ldmatrix lane addressing
    const int arow = wm * 32 + (lid & 15);
    const int achp = lid >> 4;
    const int bi = lid >> 3;                   // 0..3
    const int bnt = bi >> 1, bkh = bi & 1;
    const int brow = wn * 64 + bnt * 8 + (lid & 7);
    const int bsw  = lid & 7;

    float acc[2][8][4];
#pragma unroll
    for (int i = 0; i < 2; i++)
#pragma unroll
        for (int j = 0; j < 8; j++)
#pragma unroll
            for (int r = 0; r < 4; r++) acc[i][j][r] = 0.0f;

    // A prefetch registers (one chunk ahead)
    uint4 aR[4];
    uint32_t sR[4];

    auto ldgA = [&](int chunk) {
        int ktap = chunk >> 2, ct = chunk & 3;
        int delta = (ktap / 3 - 1) * WW + (ktap % 3 - 1);
#pragma unroll
        for (int i = 0; i < 4; i++) {
            int u = tid + i * 256;
            int fr = u >> 3, fg = u & 7;
            int nb = p0 + fr + delta; nb = nb < 0 ? 0 : (nb >= P ? P - 1 : nb);
            aR[i] = g_xf[(ct * P + nb) * 8 + (fg ^ (nb & 7))];
            sR[i] = g_selh2[(p0 + fr) * 9 + ktap];
        }
    };
    auto stsA = [&](int s) {
        char* st = smem + s * STAGE;
#pragma unroll
        for (int i = 0; i < 4; i++) {
            int u = tid + i * 256;
            int fr = u >> 3, fg = u & 7;
            uint4 v = aR[i];
            v.x = hmul2u(v.x, sR[i]);
            v.y = hmul2u(v.y, sR[i]);
            v.z = hmul2u(v.z, sR[i]);
            v.w = hmul2u(v.w, sR[i]);
            *(uint4*)(st + fr * 128 + fg * 16) = v;
        }
    };
    auto cpB = [&](int chunk, int s) {
        uint32_t st = sb + s * STAGE;
        const uint4* wp = g_w + (size_t)(chunk * 4 + nblk * 2) * 512;
#pragma unroll
        for (int i = 0; i < 4; i++)
            CPA(st + 16384 + (tid + i * 256) * 16, wp + tid + i * 256);
        asm volatile("cp.async.commit_group;" ::: "memory");
    };

    auto compute = [&](int chunk, int s) {
        uint32_t st = sb + s * STAGE;
        int ktap = chunk >> 2;
        int delta = (ktap / 3 - 1) * WW + (ktap % 3 - 1);
        int asw = (arow + delta + 128) & 7;       // tap-shifted swizzle phase
        uint32_t Ap = st, Bp = st + 16384;
#pragma unroll
        for (int ks = 0; ks < 4; ks++) {
            uint32_t a[2][4], bfr[8][2];
#pragma unroll
            for (int mt = 0; mt < 2; mt++) {
                uint32_t off = (uint32_t)(arow + mt * 16) * 128
                             + (((ks * 2 + achp) ^ asw) << 4);
                LDSM4(a[mt], Ap + off);
            }
#pragma unroll
            for (int ntp = 0; ntp < 4; ntp++) {
                uint32_t off = (uint32_t)(brow + ntp * 16) * 128
                             + (((ks * 2 + bkh) ^ bsw) << 4);
                uint32_t r[4];
                LDSM4(r, Bp + off);
                bfr[ntp*2+0][0] = r[0]; bfr[ntp*2+0][1] = r[1];
                bfr[ntp*2+1][0] = r[2]; bfr[ntp*2+1][1] = r[3];
            }
#pragma unroll
            for (int mt = 0; mt < 2; mt++)
#pragma unroll
                for (int nt = 0; nt < 8; nt++)
                    MMA(acc[mt][nt], a[mt], bfr[nt]);
        }
    };

    // prologue: stage 0 filled, A(c0+1) in regs
    ldgA(c0);
    stsA(0);
    cpB(c0, 0);
    ldgA(c0 + 1);
    asm volatile("cp.async.wait_group 0;" ::: "memory");
    __syncthreads();

#pragma unroll 1
    for (int j = 0; j < CPK; j++) {
        int c = c0 + j;
        int s = j & 1;
        if (j + 1 < CPK) cpB(c + 1, s ^ 1);        // B async into other stage
        compute(c, s);
        if (j + 1 < CPK) {
            stsA(s ^ 1);                           // sel-folded A for c+1
            if (j + 2 < CPK) ldgA(c + 2);          // prefetch next A into regs
            asm volatile("cp.async.wait_group 0;" ::: "memory");
        }
        __syncthreads();
    }

    // epilogue -> partial plane
    float* outp = g_part[kz];
#pragma unroll
    for (int mt = 0; mt < 2; mt++) {
        int r0 = p0 + wm * 32 + mt * 16 + (lid >> 2);
#pragma unroll
        for (int nt = 0; nt < 8; nt++) {
            int col = nblk * 128 + wn * 64 + nt * 8 + (lid & 3) * 2;
            float2* d0 = (float2*)(outp + (size_t)r0 * DIM + col);
            float2* d1 = (float2*)(outp + (size_t)(r0 + 8) * DIM + col);
            *d0 = make_float2(acc[mt][nt][0], acc[mt][nt][1]);
            *d1 = make_float2(acc[mt][nt][2], acc[mt][nt][3]);
        }
    }
}

// ---------------------------------------------------------------- reduce partials
__global__ void reduce_k(float* __restrict__ out)
{
    int i = blockIdx.x * blockDim.x + threadIdx.x;   // P*DIM/4 float4s
    const float4* p0 = (const float4*)g_part[0];
    const float4* p1 = (const float4*)g_part[1];
    float4 a = p0[i], b = p1[i];
    ((float4*)out)[i] = make_float4(a.x + b.x, a.y + b.y, a.z + b.z, a.w + b.w);
}

// ---------------------------------------------------------------- launch
extern "C" void kernel_launch(void* const* d_in, const int* in_sizes, int n_in,
                              void* d_out, int out_size)
{
    const float* x   = (const float*)d_in[0];
    const float* seg = (const float*)d_in[1];
    const float* wgt = (const float*)d_in[2];
    float* out = (float*)d_out;

    cudaFuncSetAttribute(pconv_mma, cudaFuncAttributeMaxDynamicSharedMemorySize,
                         NSTAGE * STAGE);

    prep_all<<<3888, 256>>>(x, seg, wgt);

    dim3 grid(P / 128, 2, KSPLIT);
    pconv_mma<<<grid, 256, NSTAGE * STAGE>>>();

    reduce_k<<<(P * DIM / 4) / 256, 256>>>(out);
}

// round 16
// speedup vs baseline: 1.5932x; 1.1755x over previous
#include <cuda_runtime.h>
#include <cuda_fp16.h>
#include <cstdint>

// ---------------------------------------------------------------- constants
#define HH 80
#define WW 80
#define CH 256
#define NC 22
#define DIM 256
#define P 25600              // 4*80*80 pixels
// A window: rows p0-81 .. p0+208 (290 rows x 128B)
#define WOFF 81
#define WROWS 290
#define AWIN 37376           // 290*128 = 37120, padded
#define BSTAGE 16384
#define SMEM_TOTAL (AWIN + 2 * BSTAGE)   // 70144

// device scratch
__device__ uint32_t g_selh2[P * 9];    // sel*norm as broadcast half2
__device__ uint4 g_w[144 * 512];       // weight fp16 smem-images (pre-swizzled 8KB blocks)
__device__ uint4 g_xf[4 * P * 8];      // x fp16, [ct][p][g] 16B groups

// ---------------------------------------------------------------- helpers
static __device__ __forceinline__ uint32_t smem_u32(const void* p) {
    uint32_t a;
    asm("{ .reg .u64 t; cvta.to.shared.u64 t, %1; cvt.u32.u64 %0, t; }" : "=r"(a) : "l"(p));
    return a;
}

#define LDSM4(r, addr) \
    asm volatile("ldmatrix.sync.aligned.m8n8.x4.shared.b16 {%0,%1,%2,%3},[%4];" \
        : "=r"((r)[0]), "=r"((r)[1]), "=r"((r)[2]), "=r"((r)[3]) : "r"(addr))
#define MMA(acc, a, b) \
    asm volatile("mma.sync.aligned.m16n8k16.row.col.f32.f16.f16.f32 " \
        "{%0,%1,%2,%3},{%4,%5,%6,%7},{%8,%9},{%0,%1,%2,%3};" \
        : "+f"((acc)[0]), "+f"((acc)[1]), "+f"((acc)[2]), "+f"((acc)[3]) \
        : "r"((a)[0]), "r"((a)[1]), "r"((a)[2]), "r"((a)[3]), "r"((b)[0]), "r"((b)[1]))
#define CPA(dst, src) \
    asm volatile("cp.async.cg.shared.global [%0], [%1], 16;" :: "r"(dst), "l"(src))

static __device__ __forceinline__ uint32_t hmul2u(uint32_t a, uint32_t s) {
    uint32_t r;
    asm("mul.rn.f16x2 %0, %1, %2;" : "=r"(r) : "r"(a), "r"(s));
    return r;
}
static __device__ __forceinline__ int clampP(int v) {
    return v < 0 ? 0 : (v >= P ? P - 1 : v);
}

// ---------------------------------------------------------------- fused prep kernel
// blocks [0,400): selnorm (4 lanes/pixel) -> g_selh2
// blocks [400,3600): x -> fp16
// blocks [3600,3888): weight -> fp16 smem-image (coalesced: d fastest)
__global__ void prep_all(const float* __restrict__ x,
                         const float* __restrict__ seg,
                         const float* __restrict__ wgt)
{
    int b = blockIdx.x;
    if (b < 400) {
        // ---- selnorm ----
        int gid = b * 256 + threadIdx.x;       // P*4 threads
        int p = gid >> 2, q = gid & 3;
        int w = p % WW, h = (p / WW) % HH;
        int c0 = q * 6;
        int ncl = (q == 3) ? 4 : 6;

        const float* cp_ = seg + (size_t)p * NC + c0;
        float cv[6];
#pragma unroll
        for (int i = 0; i < 6; i++) cv[i] = (i < ncl) ? cp_[i] : -1e30f;

        float m = cv[0];
#pragma unroll
        for (int i = 1; i < 6; i++) m = fmaxf(m, cv[i]);
        m = fmaxf(m, __shfl_xor_sync(0xffffffffu, m, 1));
        m = fmaxf(m, __shfl_xor_sync(0xffffffffu, m, 2));

        float sel[9];
        int cnt = 0;
#pragma unroll
        for (int k = 0; k < 9; k++) {
            int dh = k / 3 - 1, dw = k % 3 - 1;
            int hh = h + dh, ww = w + dw;
            float s = 0.0f;
            if (hh >= 0 && hh < HH && ww >= 0 && ww < WW) {
                const float* nb = seg + (size_t)(p + dh * WW + dw) * NC + c0;
#pragma unroll
                for (int i = 0; i < 6; i++)
                    if (i < ncl && cv[i] == m) s += nb[i];
            }
            s += __shfl_xor_sync(0xffffffffu, s, 1);
            s += __shfl_xor_sync(0xffffffffu, s, 2);
            sel[k] = s;
            if (s != 0.0f) cnt++;
        }
        float nrm = (cnt > 0) ? 9.0f / (float)cnt : 0.0f;
        for (int k = q; k < 9; k += 4) {
            __half hv = __float2half_rn(sel[k] * nrm);
            uint32_t u = (uint32_t)__half_as_ushort(hv);
            g_selh2[p * 9 + k] = u | (u << 16);
        }
    } else if (b < 3600) {
        // ---- x -> fp16 ----
        int gid = (b - 400) * 256 + threadIdx.x;   // P*32 threads
        int g8 = gid & 31;
        int p  = gid >> 5;
        int c0 = g8 * 8;
        int ct = c0 >> 6, g = (c0 >> 3) & 7;

        const float* src = x + (size_t)p * CH + c0;
        uint32_t h4[4];
#pragma unroll
        for (int j = 0; j < 4; j++) {
            __half h0 = __float2half_rn(src[2*j]);
            __half h1 = __float2half_rn(src[2*j+1]);
            h4[j] = (uint32_t)__half_as_ushort(h0) | ((uint32_t)__half_as_ushort(h1) << 16);
        }
        g_xf[(ct * P + p) * 8 + g] = make_uint4(h4[0], h4[1], h4[2], h4[3]);
    } else {
        // ---- weight -> fp16 pre-swizzled image (d varies fastest: coalesced) ----
        int id = (b - 3600) * 256 + threadIdx.x;   // 73728 threads
        int row  = id & 63;            // d_local (fastest)
        int cc8  = (id >> 6) & 7;
        int blk  = id >> 9;            // 0..143
        int nb4  = blk & 3;
        int chunk = blk >> 2;
        int ktap = chunk >> 2, ct = chunk & 3;
        int d  = nb4 * 64 + row;
        int c0 = ct * 64 + cc8 * 8;

        uint32_t h4[4];
#pragma unroll
        for (int j = 0; j < 4; j++) {
            float v0 = wgt[(size_t)(c0 + 2*j)     * (9 * DIM) + ktap * DIM + d];
            float v1 = wgt[(size_t)(c0 + 2*j + 1) * (9 * DIM) + ktap * DIM + d];
            __half h0 = __float2half_rn(v0);
            __half h1 = __float2half_rn(v1);
            h4[j] = (uint32_t)__half_as_ushort(h0) | ((uint32_t)__half_as_ushort(h1) << 16);
        }
        int idx = blk * 512 + row * 8 + (cc8 ^ (row & 7));
        g_w[idx] = make_uint4(h4[0], h4[1], h4[2], h4[3]);
    }
}

// ---------------------------------------------------------------- HMMA implicit GEMM
// CTA 128(M) x 128(N), 256 threads, 8 warps (4M x 2N), warp tile 32x64.
// Loop: ct (4 channel quarters) x ktap (9 taps). Per ct, ONE 290-row x window
// lives in smem; each tap reads a shifted view (row + delta + WOFF). sel
// folded into A fragments (HMUL2). B double-buffered via cp.async. 2 CTAs/SM.
__global__ __launch_bounds__(256, 2) void pconv_mma(float* __restrict__ out)
{
    extern __shared__ __align__(1024) char smem[];
    const uint32_t sb = smem_u32(smem);
    const int tid = threadIdx.x, wid = tid >> 5, lid = tid & 31;
    const int p0 = blockIdx.x * 128;
    const int nblk = blockIdx.y;            // 0..1 (128-wide N block)
    const int wm = wid & 3, wn = wid >> 2;  // 4 M-quarters x 2 N-halves(64)

    // ldmatrix lane addressing
    const int arow = wm * 32 + (lid & 15);
    const int achp = lid >> 4;
    const int bi = lid >> 3;                   // 0..3
    const int bnt = bi >> 1, bkh = bi & 1;
    const int brow = wn * 64 + bnt * 8 + (lid & 7);
    const int bsw  = lid & 7;
    const int rlane = lid >> 2;

    float acc[2][8][4];
#pragma unroll
    for (int i = 0; i < 2; i++)
#pragma unroll
        for (int j = 0; j < 8; j++)
#pragma unroll
            for (int r = 0; r < 4; r++) acc[i][j][r] = 0.0f;

    // fill the per-ct A window: 290 rows x 8 groups = 2320 uint4
    auto fillA = [&](int ct) {
#pragma unroll 1
        for (int u = tid; u < WROWS * 8; u += 256) {
            int fr = u >> 3, fg = u & 7;
            int nb = clampP(p0 - WOFF + fr);
            CPA(sb + fr * 128 + fg * 16,
                g_xf + (size_t)(ct * P + nb) * 8 + (fg ^ (fr & 7)));
        }
    };
    auto cpB = [&](int ct, int ktap, int s) {
        uint32_t st = sb + AWIN + s * BSTAGE;
        int chunk = ktap * 4 + ct;
        const uint4* wp = g_w + (size_t)(chunk * 4 + nblk * 2) * 512;
#pragma unroll
        for (int i = 0; i < 4; i++)
            CPA(st + (tid + i * 256) * 16, wp + tid + i * 256);
        asm volatile("cp.async.commit_group;" ::: "memory");
    };

    auto compute = [&](int ct, int ktap, int s) {
        int delta = (ktap / 3 - 1) * WW + (ktap % 3 - 1);
        int wbase = delta + WOFF;                 // window row offset
        int asw = (arow + wbase) & 7;             // swizzle phase (window row)
        uint32_t Ap = sb;
        uint32_t Bp = sb + AWIN + s * BSTAGE;

        // per-tap sel (broadcast half2)
        uint32_t sv[2][2];
#pragma unroll
        for (int mt = 0; mt < 2; mt++) {
            int r0 = p0 + wm * 32 + mt * 16 + rlane;
            sv[mt][0] = g_selh2[r0 * 9 + ktap];
            sv[mt][1] = g_selh2[(r0 + 8) * 9 + ktap];
        }

#pragma unroll
        for (int ks = 0; ks < 4; ks++) {
            uint32_t a[2][4], bfr[8][2];
#pragma unroll
            for (int mt = 0; mt < 2; mt++) {
                uint32_t off = (uint32_t)(arow + mt * 16 + wbase) * 128
                             + (((ks * 2 + achp) ^ asw) << 4);
                LDSM4(a[mt], Ap + off);
                // fold sel: a0,a2 = row lo; a1,a3 = row hi
                a[mt][0] = hmul2u(a[mt][0], sv[mt][0]);
                a[mt][2] = hmul2u(a[mt][2], sv[mt][0]);
                a[mt][1] = hmul2u(a[mt][1], sv[mt][1]);
                a[mt][3] = hmul2u(a[mt][3], sv[mt][1]);
            }
#pragma unroll
            for (int ntp = 0; ntp < 4; ntp++) {
                uint32_t off = (uint32_t)(brow + ntp * 16) * 128
                             + (((ks * 2 + bkh) ^ bsw) << 4);
                uint32_t r[4];
                LDSM4(r, Bp + off);
                bfr[ntp*2+0][0] = r[0]; bfr[ntp*2+0][1] = r[1];
                bfr[ntp*2+1][0] = r[2]; bfr[ntp*2+1][1] = r[3];
            }
#pragma unroll
            for (int mt = 0; mt < 2; mt++)
#pragma unroll
                for (int nt = 0; nt < 8; nt++)
                    MMA(acc[mt][nt], a[mt], bfr[nt]);
        }
    };

#pragma unroll 1
    for (int ct = 0; ct < 4; ct++) {
        __syncthreads();             // all readers of previous window/B done
        fillA(ct);                   // A window cp.async (uncommitted)
        cpB(ct, 0, 0);               // commits the group (A + B0)
        asm volatile("cp.async.wait_group 0;" ::: "memory");
        __syncthreads();

#pragma unroll 1
        for (int ktap = 0; ktap < 9; ktap++) {
            int s = ktap & 1;
            if (ktap + 1 < 9) cpB(ct, ktap + 1, s ^ 1);
            compute(ct, ktap, s);
            if (ktap + 1 < 9) {
                asm volatile("cp.async.wait_group 0;" ::: "memory");
                __syncthreads();     // publish B(t+1); readers of s^1 done
            }
        }
    }

    // epilogue
#pragma unroll
    for (int mt = 0; mt < 2; mt++) {
        int r0 = p0 + wm * 32 + mt * 16 + rlane;
#pragma unroll
        for (int nt = 0; nt < 8; nt++) {
            int col = nblk * 128 + wn * 64 + nt * 8 + (lid & 3) * 2;
            float2* d0 = (float2*)(out + (size_t)r0 * DIM + col);
            float2* d1 = (float2*)(out + (size_t)(r0 + 8) * DIM + col);
            *d0 = make_float2(acc[mt][nt][0], acc[mt][nt][1]);
            *d1 = make_float2(acc[mt][nt][2], acc[mt][nt][3]);
        }
    }
}

// ---------------------------------------------------------------- launch
extern "C" void kernel_launch(void* const* d_in, const int* in_sizes, int n_in,
                              void* d_out, int out_size)
{
    const float* x   = (const float*)d_in[0];
    const float* seg = (const float*)d_in[1];
    const float* wgt = (const float*)d_in[2];
    float* out = (float*)d_out;

    cudaFuncSetAttribute(pconv_mma, cudaFuncAttributeMaxDynamicSharedMemorySize,
                         SMEM_TOTAL);

    prep_all<<<3888, 256>>>(x, seg, wgt);

    dim3 grid(P / 128, 2);
    pconv_mma<<<grid, 256, SMEM_TOTAL>>>(out);
}

// round 17
// speedup vs baseline: 1.6109x; 1.0111x over previous
#include <cuda_runtime.h>
#include <cuda_fp16.h>
#include <cstdint>

// ---------------------------------------------------------------- constants
#define HH 80
#define WW 80
#define CH 256
#define NC 22
#define DIM 256
#define P 25600              // 4*80*80 pixels
// A window: rows p0-81 .. p0+208 (290 rows x 128B)
#define WOFF 81
#define WROWS 290
#define AWIN 37376           // 290*128 = 37120, padded
#define BSTAGE 16384
#define NBST 3
#define SMEM_TOTAL (AWIN + NBST * BSTAGE)   // 86528

// device scratch
__device__ uint32_t g_selh2[P * 9];    // sel*norm as broadcast half2
__device__ uint4 g_w[144 * 512];       // weight fp16 smem-images (pre-swizzled 8KB blocks)
__device__ uint4 g_xf[4 * P * 8];      // x fp16, [ct][p][g] 16B groups

// ---------------------------------------------------------------- helpers
static __device__ __forceinline__ uint32_t smem_u32(const void* p) {
    uint32_t a;
    asm("{ .reg .u64 t; cvta.to.shared.u64 t, %1; cvt.u32.u64 %0, t; }" : "=r"(a) : "l"(p));
    return a;
}

#define LDSM4(r, addr) \
    asm volatile("ldmatrix.sync.aligned.m8n8.x4.shared.b16 {%0,%1,%2,%3},[%4];" \
        : "=r"((r)[0]), "=r"((r)[1]), "=r"((r)[2]), "=r"((r)[3]) : "r"(addr))
#define MMA(acc, a, b) \
    asm volatile("mma.sync.aligned.m16n8k16.row.col.f32.f16.f16.f32 " \
        "{%0,%1,%2,%3},{%4,%5,%6,%7},{%8,%9},{%0,%1,%2,%3};" \
        : "+f"((acc)[0]), "+f"((acc)[1]), "+f"((acc)[2]), "+f"((acc)[3]) \
        : "r"((a)[0]), "r"((a)[1]), "r"((a)[2]), "r"((a)[3]), "r"((b)[0]), "r"((b)[1]))
#define CPA(dst, src) \
    asm volatile("cp.async.cg.shared.global [%0], [%1], 16;" :: "r"(dst), "l"(src))
#define CPW(n) \
    asm volatile("cp.async.wait_group %0;" :: "n"(n) : "memory")

static __device__ __forceinline__ uint32_t hmul2u(uint32_t a, uint32_t s) {
    uint32_t r;
    asm("mul.rn.f16x2 %0, %1, %2;" : "=r"(r) : "r"(a), "r"(s));
    return r;
}
static __device__ __forceinline__ int clampP(int v) {
    return v < 0 ? 0 : (v >= P ? P - 1 : v);
}

// ---------------------------------------------------------------- fused prep kernel
// blocks [0,400): selnorm (4 lanes/pixel) -> g_selh2
// blocks [400,3600): x -> fp16 (float4 loads)
// blocks [3600,3888): weight -> fp16 smem-image (coalesced: d fastest)
__global__ void prep_all(const float* __restrict__ x,
                         const float* __restrict__ seg,
                         const float* __restrict__ wgt)
{
    int b = blockIdx.x;
    if (b < 400) {
        // ---- selnorm ----
        int gid = b * 256 + threadIdx.x;       // P*4 threads
        int p = gid >> 2, q = gid & 3;
        int w = p % WW, h = (p / WW) % HH;
        int c0 = q * 6;
        int ncl = (q == 3) ? 4 : 6;

        const float* cp_ = seg + (size_t)p * NC + c0;
        float cv[6];
#pragma unroll
        for (int i = 0; i < 6; i++) cv[i] = (i < ncl) ? cp_[i] : -1e30f;

        float m = cv[0];
#pragma unroll
        for (int i = 1; i < 6; i++) m = fmaxf(m, cv[i]);
        m = fmaxf(m, __shfl_xor_sync(0xffffffffu, m, 1));
        m = fmaxf(m, __shfl_xor_sync(0xffffffffu, m, 2));

        float sel[9];
        int cnt = 0;
#pragma unroll
        for (int k = 0; k < 9; k++) {
            int dh = k / 3 - 1, dw = k % 3 - 1;
            int hh = h + dh, ww = w + dw;
            float s = 0.0f;
            if (hh >= 0 && hh < HH && ww >= 0 && ww < WW) {
                const float* nb = seg + (size_t)(p + dh * WW + dw) * NC + c0;
#pragma unroll
                for (int i = 0; i < 6; i++)
                    if (i < ncl && cv[i] == m) s += nb[i];
            }
            s += __shfl_xor_sync(0xffffffffu, s, 1);
            s += __shfl_xor_sync(0xffffffffu, s, 2);
            sel[k] = s;
            if (s != 0.0f) cnt++;
        }
        float nrm = (cnt > 0) ? 9.0f / (float)cnt : 0.0f;
        for (int k = q; k < 9; k += 4) {
            __half hv = __float2half_rn(sel[k] * nrm);
            uint32_t u = (uint32_t)__half_as_ushort(hv);
            g_selh2[p * 9 + k] = u | (u << 16);
        }
    } else if (b < 3600) {
        // ---- x -> fp16 (two LDG.128 per thread) ----
        int gid = (b - 400) * 256 + threadIdx.x;   // P*32 threads
        int g8 = gid & 31;
        int p  = gid >> 5;
        int c0 = g8 * 8;
        int ct = c0 >> 6, g = (c0 >> 3) & 7;

        const float4* s4 = (const float4*)(x + (size_t)p * CH + c0);
        float4 v0 = s4[0], v1 = s4[1];
        float vv[8] = { v0.x, v0.y, v0.z, v0.w, v1.x, v1.y, v1.z, v1.w };
        uint32_t h4[4];
#pragma unroll
        for (int j = 0; j < 4; j++) {
            __half h0 = __float2half_rn(vv[2*j]);
            __half h1 = __float2half_rn(vv[2*j+1]);
            h4[j] = (uint32_t)__half_as_ushort(h0) | ((uint32_t)__half_as_ushort(h1) << 16);
        }
        g_xf[(ct * P + p) * 8 + g] = make_uint4(h4[0], h4[1], h4[2], h4[3]);
    } else {
        // ---- weight -> fp16 pre-swizzled image (d varies fastest: coalesced) ----
        int id = (b - 3600) * 256 + threadIdx.x;   // 73728 threads
        int row  = id & 63;            // d_local (fastest)
        int cc8  = (id >> 6) & 7;
        int blk  = id >> 9;            // 0..143
        int nb4  = blk & 3;
        int chunk = blk >> 2;
        int ktap = chunk >> 2, ct = chunk & 3;
        int d  = nb4 * 64 + row;
        int c0 = ct * 64 + cc8 * 8;

        uint32_t h4[4];
#pragma unroll
        for (int j = 0; j < 4; j++) {
            float v0 = wgt[(size_t)(c0 + 2*j)     * (9 * DIM) + ktap * DIM + d];
            float v1 = wgt[(size_t)(c0 + 2*j + 1) * (9 * DIM) + ktap * DIM + d];
            __half h0 = __float2half_rn(v0);
            __half h1 = __float2half_rn(v1);
            h4[j] = (uint32_t)__half_as_ushort(h0) | ((uint32_t)__half_as_ushort(h1) << 16);
        }
        int idx = blk * 512 + row * 8 + (cc8 ^ (row & 7));
        g_w[idx] = make_uint4(h4[0], h4[1], h4[2], h4[3]);
    }
}

// ---------------------------------------------------------------- HMMA implicit GEMM
// CTA 128(M) x 128(N), 256 threads, 8 warps (4M x 2N), warp tile 32x64.
// Loop: ct (4 channel quarters) x ktap (9 taps). Per ct, ONE 290-row x window
// in smem; each tap reads a shifted view. sel folded into A fragments.
// B through a 3-stage cp.async ring (wait_group <= 2 in steady state).
__global__ __launch_bounds__(256, 2) void pconv_mma(float* __restrict__ out)
{
    extern __shared__ __align__(1024) char smem[];
    const uint32_t sb = smem_u32(smem);
    const int tid = threadIdx.x, wid = tid >> 5, lid = tid & 31;
    const int p0 = blockIdx.x * 128;
    const int nblk = blockIdx.y;            // 0..1 (128-wide N block)
    const int wm = wid & 3, wn = wid >> 2;  // 4 M-quarters x 2 N-halves(64)

    // ldmatrix lane addressing
    const int arow = wm * 32 + (lid & 15);
    const int achp = lid >> 4;
    const int bi = lid >> 3;                   // 0..3
    const int bnt = bi >> 1, bkh = bi & 1;
    const int brow = wn * 64 + bnt * 8 + (lid & 7);
    const int bsw  = lid & 7;
    const int rlane = lid >> 2;

    float acc[2][8][4];
#pragma unroll
    for (int i = 0; i < 2; i++)
#pragma unroll
        for (int j = 0; j < 8; j++)
#pragma unroll
            for (int r = 0; r < 4; r++) acc[i][j][r] = 0.0f;

    // fill the per-ct A window: 290 rows x 8 groups = 2320 uint4
    auto fillA = [&](int ct) {
#pragma unroll 1
        for (int u = tid; u < WROWS * 8; u += 256) {
            int fr = u >> 3, fg = u & 7;
            int nb = clampP(p0 - WOFF + fr);
            CPA(sb + fr * 128 + fg * 16,
                g_xf + (size_t)(ct * P + nb) * 8 + (fg ^ (fr & 7)));
        }
    };
    auto cpB = [&](int ct, int ktap, int s) {
        uint32_t st = sb + AWIN + s * BSTAGE;
        int chunk = ktap * 4 + ct;
        const uint4* wp = g_w + (size_t)(chunk * 4 + nblk * 2) * 512;
#pragma unroll
        for (int i = 0; i < 4; i++)
            CPA(st + (tid + i * 256) * 16, wp + tid + i * 256);
        asm volatile("cp.async.commit_group;" ::: "memory");
    };

#pragma unroll 1
    for (int ct = 0; ct < 4; ct++) {
        __syncthreads();             // all readers of previous window + B stages done
        fillA(ct);                   // uncommitted
        cpB(ct, 0, 0);               // commits group (A window + B0)
        cpB(ct, 1, 1);               // group (B1)
        CPW(1);                      // A window + B0 landed; B1 may fly
        __syncthreads();

#pragma unroll 1
        for (int ktap = 0; ktap < 9; ktap++) {
            const int s = ktap % NBST;
            if (ktap > 0) __syncthreads();   // compute(ktap-1) readers done before
                                             // overwriting stage (ktap+2)%3 == (ktap-1)%3
            if (ktap + 2 <= 8) cpB(ct, ktap + 2, (ktap + 2) % NBST);

            // per-tap sel (issue LDGs before the wait so latency overlaps)
            uint32_t sv[2][2];
#pragma unroll
            for (int mt = 0; mt < 2; mt++) {
                int r0 = p0 + wm * 32 + mt * 16 + rlane;
                sv[mt][0] = g_selh2[r0 * 9 + ktap];
                sv[mt][1] = g_selh2[(r0 + 8) * 9 + ktap];
            }

            // wait for B(ktap); allow younger fills in flight
            {
                int rem = (ktap + 1 <= 8 ? 1 : 0) + (ktap + 2 <= 8 ? 1 : 0);
                if (rem == 2)      CPW(2);
                else if (rem == 1) CPW(1);
                else               CPW(0);
            }

            const int delta = (ktap / 3 - 1) * WW + (ktap % 3 - 1);
            const int wbase = delta + WOFF;
            const int asw = (arow + wbase) & 7;
            const uint32_t Ap = sb;
            const uint32_t Bp = sb + AWIN + s * BSTAGE;

#pragma unroll
            for (int ks = 0; ks < 4; ks++) {
                uint32_t a[2][4], bfr[8][2];
#pragma unroll
                for (int mt = 0; mt < 2; mt++) {
                    uint32_t off = (uint32_t)(arow + mt * 16 + wbase) * 128
                                 + (((ks * 2 + achp) ^ asw) << 4);
                    LDSM4(a[mt], Ap + off);
                    a[mt][0] = hmul2u(a[mt][0], sv[mt][0]);
                    a[mt][2] = hmul2u(a[mt][2], sv[mt][0]);
                    a[mt][1] = hmul2u(a[mt][1], sv[mt][1]);
                    a[mt][3] = hmul2u(a[mt][3], sv[mt][1]);
                }
#pragma unroll
                for (int ntp = 0; ntp < 4; ntp++) {
                    uint32_t off = (uint32_t)(brow + ntp * 16) * 128
                                 + (((ks * 2 + bkh) ^ bsw) << 4);
                    uint32_t r[4];
                    LDSM4(r, Bp + off);
                    bfr[ntp*2+0][0] = r[0]; bfr[ntp*2+0][1] = r[1];
                    bfr[ntp*2+1][0] = r[2]; bfr[ntp*2+1][1] = r[3];
                }
#pragma unroll
                for (int mt = 0; mt < 2; mt++)
#pragma unroll
                    for (int nt = 0; nt < 8; nt++)
                        MMA(acc[mt][nt], a[mt], bfr[nt]);
            }
        }
    }

    // epilogue
#pragma unroll
    for (int mt = 0; mt < 2; mt++) {
        int r0 = p0 + wm * 32 + mt * 16 + rlane;
#pragma unroll
        for (int nt = 0; nt < 8; nt++) {
            int col = nblk * 128 + wn * 64 + nt * 8 + (lid & 3) * 2;
            float2* d0 = (float2*)(out + (size_t)r0 * DIM + col);
            float2* d1 = (float2*)(out + (size_t)(r0 + 8) * DIM + col);
            *d0 = make_float2(acc[mt][nt][0], acc[mt][nt][1]);
            *d1 = make_float2(acc[mt][nt][2], acc[mt][nt][3]);
        }
    }
}

// ---------------------------------------------------------------- launch
extern "C" void kernel_launch(void* const* d_in, const int* in_sizes, int n_in,
                              void* d_out, int out_size)
{
    const float* x   = (const float*)d_in[0];
    const float* seg = (const float*)d_in[1];
    const float* wgt = (const float*)d_in[2];
    float* out = (float*)d_out;

    cudaFuncSetAttribute(pconv_mma, cudaFuncAttributeMaxDynamicSharedMemorySize,
                         SMEM_TOTAL);

    prep_all<<<3888, 256>>>(x, seg, wgt);

    dim3 grid(P / 128, 2);
    pconv_mma<<<grid, 256, SMEM_TOTAL>>>(out);
}